// round 17
// baseline (speedup 1.0000x reference)
#include <cuda_runtime.h>
#include <cstdint>

// MeanAggregator: out[i] = sum_{j in edges[i]} nodes[edges[i][j]] / n_nodes
// Shapes: N = 40000, DEG = 16, D = 128 (fp32); edges buffer is int32.
//
// R17: all register-LDG variants (R4-R16) are capped by the per-SM L1tex
// outstanding-line queue (~248 lines / ~600cyc loaded latency = 0.41
// lines/cyc = measured 0.39). cp.async (LDGSTS) tracks completion via
// commit-groups, not the register scoreboard, with no observed depth cap.
// Hybrid: per node, 8 neighbors via LDG.128 (register path) and 8 via
// cp.async.cg into a per-warp smem slice — two independent outstanding-
// capacity budgets running concurrently.

#define D_FEAT 128
#define D_VEC (D_FEAT / 4)   // 32 float4 per row = 1 per lane
#define DEG_FAST 16
#define ASYNC_ROWS 8         // neighbors fetched via cp.async
#define LDG_ROWS 8           // neighbors fetched via register LDG
#define SMS 148
#define BLOCKS_PER_SM 4
#define THREADS 256
#define WARPS_PER_BLOCK (THREADS / 32)

// Per-warp smem staging: 8 rows x 512B = 4KB; 8 warps -> 32KB static.
__global__ __launch_bounds__(THREADS, BLOCKS_PER_SM)
void gather_mean_hybrid_kernel(
    const float4* __restrict__ nodes,   // [n_nodes * 32] float4
    const int* __restrict__ edges,      // [n_nodes * deg] int32
    float4* __restrict__ out,           // [n_nodes * 32] float4
    int n_nodes, int deg, float inv_n)
{
    __shared__ __align__(16) float sbuf[WARPS_PER_BLOCK * ASYNC_ROWS * D_FEAT];

    const int lane = threadIdx.x & 31;
    const int warp_in_block = threadIdx.x >> 5;
    const int warp_gid = (blockIdx.x * THREADS + threadIdx.x) >> 5;
    const int warp_stride = (gridDim.x * THREADS) >> 5;

    float* mybuf = sbuf + warp_in_block * (ASYNC_ROWS * D_FEAT);
    // This thread's 16B slot within each staged row (it copies AND reads the
    // same bytes, so per-thread wait_group ordering suffices).
    const uint32_t s_base =
        (uint32_t)__cvta_generic_to_shared(mybuf) + (uint32_t)lane * 16u;

    if (deg == DEG_FAST) {
        for (int node = warp_gid; node < n_nodes; node += warp_stride) {
            // Index fetch: 4 x int4 (uniform across warp -> broadcast).
            const int4* e4 = (const int4*)(edges + (long long)node * DEG_FAST);
            int idx[DEG_FAST];
#pragma unroll
            for (int q = 0; q < 4; ++q) {
                int4 a = __ldg(&e4[q]);
                idx[q * 4 + 0] = a.x; idx[q * 4 + 1] = a.y;
                idx[q * 4 + 2] = a.z; idx[q * 4 + 3] = a.w;
            }

            // Path A: launch 8 async row copies FIRST (LDGSTS queue).
#pragma unroll
            for (int r = 0; r < ASYNC_ROWS; ++r) {
                const float4* src =
                    nodes + (size_t)(unsigned)idx[LDG_ROWS + r] * D_VEC + lane;
                uint32_t dst = s_base + (uint32_t)r * (D_FEAT * 4);
                asm volatile(
                    "cp.async.cg.shared.global [%0], [%1], 16;\n"
                    :: "r"(dst), "l"(src));
            }
            asm volatile("cp.async.commit_group;\n" ::: "memory");

            // Path B: 8 register-path gathers (L1tex queue), reduced in regs.
            float4 v[LDG_ROWS];
#pragma unroll
            for (int r = 0; r < LDG_ROWS; ++r) {
                v[r] = __ldg(&nodes[(size_t)(unsigned)idx[r] * D_VEC + lane]);
            }
            float4 s0, s1, s2, s3;
            s0.x = v[0].x + v[1].x; s0.y = v[0].y + v[1].y;
            s0.z = v[0].z + v[1].z; s0.w = v[0].w + v[1].w;
            s1.x = v[2].x + v[3].x; s1.y = v[2].y + v[3].y;
            s1.z = v[2].z + v[3].z; s1.w = v[2].w + v[3].w;
            s2.x = v[4].x + v[5].x; s2.y = v[4].y + v[5].y;
            s2.z = v[4].z + v[5].z; s2.w = v[4].w + v[5].w;
            s3.x = v[6].x + v[7].x; s3.y = v[6].y + v[7].y;
            s3.z = v[6].z + v[7].z; s3.w = v[6].w + v[7].w;
            float4 acc;
            acc.x = (s0.x + s1.x) + (s2.x + s3.x);
            acc.y = (s0.y + s1.y) + (s2.y + s3.y);
            acc.z = (s0.z + s1.z) + (s2.z + s3.z);
            acc.w = (s0.w + s1.w) + (s2.w + s3.w);

            // Wait for async rows, reduce them from smem.
            asm volatile("cp.async.wait_group 0;\n" ::: "memory");
            const float4* srow = (const float4*)mybuf + lane;
#pragma unroll
            for (int r = 0; r < ASYNC_ROWS; ++r) {
                float4 w = srow[r * D_VEC];
                acc.x += w.x; acc.y += w.y; acc.z += w.z; acc.w += w.w;
            }

            out[(long long)node * D_VEC + lane] =
                make_float4(acc.x * inv_n, acc.y * inv_n,
                            acc.z * inv_n, acc.w * inv_n);
        }
    } else {
        // Generic fallback: pure register-path gathers.
        for (int node = warp_gid; node < n_nodes; node += warp_stride) {
            const int* e = edges + (long long)node * deg;
            float4 acc = make_float4(0.f, 0.f, 0.f, 0.f);
            int j = 0;
            for (; j + 4 <= deg; j += 4) {
                int i0 = __ldg(&e[j + 0]);
                int i1 = __ldg(&e[j + 1]);
                int i2 = __ldg(&e[j + 2]);
                int i3 = __ldg(&e[j + 3]);
                float4 v0 = __ldg(&nodes[(size_t)(unsigned)i0 * D_VEC + lane]);
                float4 v1 = __ldg(&nodes[(size_t)(unsigned)i1 * D_VEC + lane]);
                float4 v2 = __ldg(&nodes[(size_t)(unsigned)i2 * D_VEC + lane]);
                float4 v3 = __ldg(&nodes[(size_t)(unsigned)i3 * D_VEC + lane]);
                acc.x += (v0.x + v1.x) + (v2.x + v3.x);
                acc.y += (v0.y + v1.y) + (v2.y + v3.y);
                acc.z += (v0.z + v1.z) + (v2.z + v3.z);
                acc.w += (v0.w + v1.w) + (v2.w + v3.w);
            }
            for (; j < deg; ++j) {
                int i0 = __ldg(&e[j]);
                float4 v = __ldg(&nodes[(size_t)(unsigned)i0 * D_VEC + lane]);
                acc.x += v.x; acc.y += v.y; acc.z += v.z; acc.w += v.w;
            }
            out[(long long)node * D_VEC + lane] =
                make_float4(acc.x * inv_n, acc.y * inv_n,
                            acc.z * inv_n, acc.w * inv_n);
        }
    }
}

extern "C" void kernel_launch(void* const* d_in, const int* in_sizes, int n_in,
                              void* d_out, int out_size)
{
    const float4* nodes = (const float4*)d_in[0];
    const int* edges = (const int*)d_in[1];
    float4* out = (float4*)d_out;

    const int n_nodes = in_sizes[0] / D_FEAT;
    const int deg = in_sizes[1] / n_nodes;
    const float inv_n = 1.0f / (float)n_nodes;

    // Persistent single wave: 148 SMs x 4 blocks of 256 threads.
    const int blocks = SMS * BLOCKS_PER_SM;  // 592
    gather_mean_hybrid_kernel<<<blocks, THREADS>>>(nodes, edges, out,
                                                   n_nodes, deg, inv_n);
}